// round 15
// baseline (speedup 1.0000x reference)
#include <cuda_runtime.h>
#include <cuda_bf16.h>
#include <stdint.h>

#define Dd      1024
#define NTOK    16384
#define NLAYERS 18
#define RLORA   32
#define QGROUP  16

typedef __nv_bfloat16 bf16;

// ---------------- scratch (__device__ globals; no allocation allowed) ----------------
__device__ bf16 g_Whi[(size_t)NLAYERS * Dd * Dd];
__device__ bf16 g_Wlo[(size_t)NLAYERS * Dd * Dd];
// activation streams as hi/lo bf16 pairs
__device__ bf16 g_xh[(size_t)NTOK * Dd], g_xl[(size_t)NTOK * Dd];
__device__ bf16 g_t1h[(size_t)NTOK * Dd], g_t1l[(size_t)NTOK * Dd];
__device__ bf16 g_t2h[(size_t)NTOK * Dd], g_t2l[(size_t)NTOK * Dd];
__device__ bf16 g_h0h[(size_t)NTOK * Dd], g_h0l[(size_t)NTOK * Dd];
__device__ bf16 g_h1h[(size_t)NTOK * Dd], g_h1l[(size_t)NTOK * Dd];

// ---------------- helpers ----------------
__device__ __forceinline__ uint32_t pack_hi(float a, float b, uint32_t& lo) {
    bf16 ha = __float2bfloat16(a), hb = __float2bfloat16(b);
    __nv_bfloat162 L = __floats2bfloat162_rn(a - __bfloat162float(ha), b - __bfloat162float(hb));
    __nv_bfloat162 H = __halves2bfloat162(ha, hb);
    lo = *reinterpret_cast<uint32_t*>(&L);
    return *reinterpret_cast<uint32_t*>(&H);
}

__device__ __forceinline__ float2 recon2(uint32_t h, uint32_t l) {
    __nv_bfloat162 H = *reinterpret_cast<__nv_bfloat162*>(&h);
    __nv_bfloat162 L = *reinterpret_cast<__nv_bfloat162*>(&l);
    return make_float2(__bfloat162float(H.x) + __bfloat162float(L.x),
                       __bfloat162float(H.y) + __bfloat162float(L.y));
}

// ---------------- prep: smem-tiled dequant + LoRA fold + hi/lo split -----------------
// One CTA per (layer, group of 16 output rows). la r-chunks staged in smem.
// Thread owns o = og*16 + (tid>>4), i = (tid&15)*4 + j*64 (j=0..15, interleaved chunks
// so warp LDS128 addresses are consecutive 16B -> conflict-free).
__global__ void __launch_bounds__(256)
prep_kernel(const int* __restrict__ qw, const float* __restrict__ sc,
            const float* __restrict__ la, const float* __restrict__ lb) {
    __shared__ float la_s[8][1024];
    __shared__ float lb_s[16][32];
    const int l  = blockIdx.x >> 6;
    const int og = blockIdx.x & 63;
    const int t  = threadIdx.x;
    const int o_local = t >> 4;        // 0..15
    const int i0 = (t & 15) << 2;      // 0,4,...,60
    const int o  = og * 16 + o_local;

    if (t < 128) {  // 16 o x 32 r = 512 floats
        int oo = t >> 3;
        int rr = (t & 7) << 2;
        *reinterpret_cast<float4*>(&lb_s[oo][rr]) =
            *reinterpret_cast<const float4*>(lb + ((size_t)l * Dd + og * 16 + oo) * RLORA + rr);
    }

    const size_t wrow = ((size_t)l * Dd + o) * Dd;
    const size_t srow = ((size_t)l * Dd + o) * (Dd / QGROUP);
    float4 acc[16];
#pragma unroll
    for (int j = 0; j < 16; j++) {
        int i = i0 + (j << 6);
        int4 q = *reinterpret_cast<const int4*>(qw + wrow + i);
        float s = sc[srow + (i >> 4)];   // 4-aligned chunk never crosses a 16-group
        acc[j] = make_float4(q.x * s, q.y * s, q.z * s, q.w * s);
    }

    for (int rc = 0; rc < 4; rc++) {
        __syncthreads();   // protects la_s reuse; also orders lb_s before first use
#pragma unroll
        for (int v = 0; v < 8; v++) {   // 2048 float4 loads, 8 per thread
            int idx = v * 256 + t;
            int r = idx >> 8;
            int col = (idx & 255) << 2;
            *reinterpret_cast<float4*>(&la_s[r][col]) =
                *reinterpret_cast<const float4*>(la + ((size_t)l * RLORA + rc * 8 + r) * Dd + col);
        }
        __syncthreads();
#pragma unroll
        for (int r = 0; r < 8; r++) {
            float b = lb_s[o_local][rc * 8 + r];
#pragma unroll
            for (int j = 0; j < 16; j++) {
                const float4 v = *reinterpret_cast<const float4*>(&la_s[r][i0 + (j << 6)]);
                acc[j].x += b * v.x; acc[j].y += b * v.y;
                acc[j].z += b * v.z; acc[j].w += b * v.w;
            }
        }
    }

#pragma unroll
    for (int j = 0; j < 16; j++) {
        int i = i0 + (j << 6);
        uint32_t l01, l23;
        uint32_t h01 = pack_hi(acc[j].x, acc[j].y, l01);
        uint32_t h23 = pack_hi(acc[j].z, acc[j].w, l23);
        *reinterpret_cast<uint2*>(&g_Whi[wrow + i]) = make_uint2(h01, h23);
        *reinterpret_cast<uint2*>(&g_Wlo[wrow + i]) = make_uint2(l01, l23);
    }
}

// ---------------- split x (fp32 -> hi/lo bf16 streams) ----------------
__global__ void split_kernel(const float* __restrict__ x, bf16* __restrict__ hi,
                             bf16* __restrict__ lo) {
    size_t i = ((size_t)blockIdx.x * blockDim.x + threadIdx.x) * 4;
    float4 v = *reinterpret_cast<const float4*>(x + i);
    uint32_t l01, l23;
    uint32_t h01 = pack_hi(v.x, v.y, l01);
    uint32_t h23 = pack_hi(v.z, v.w, l23);
    *reinterpret_cast<uint2*>(hi + i) = make_uint2(h01, h23);
    *reinterpret_cast<uint2*>(lo + i) = make_uint2(l01, l23);
}

// ---------------- GEMM helpers ----------------
// smem tile row = 128B: chunks 0-3 = hi (32 k-elems), 4-7 = lo. Swizzle: chunk ^= (row&7).
__device__ __forceinline__ uint32_t swz(int row, int chunk) {
    return (uint32_t)((row << 7) + ((chunk ^ (row & 7)) << 4));
}

__device__ __forceinline__ void ldsm4(uint32_t& r0, uint32_t& r1, uint32_t& r2, uint32_t& r3,
                                      uint32_t addr) {
    asm volatile("ldmatrix.sync.aligned.m8n8.x4.shared.b16 {%0,%1,%2,%3}, [%4];\n"
                 : "=r"(r0), "=r"(r1), "=r"(r2), "=r"(r3) : "r"(addr));
}

__device__ __forceinline__ void mma16816(float* c, const uint32_t* a, const uint32_t* b) {
    asm volatile("mma.sync.aligned.m16n8k16.row.col.f32.bf16.bf16.f32 "
                 "{%0,%1,%2,%3}, {%4,%5,%6,%7}, {%8,%9}, {%0,%1,%2,%3};\n"
                 : "+f"(c[0]), "+f"(c[1]), "+f"(c[2]), "+f"(c[3])
                 : "r"(a[0]), "r"(a[1]), "r"(a[2]), "r"(a[3]), "r"(b[0]), "r"(b[1]));
}

// ---------------- GEMM: Y[M,1024] = A @ W^T (+bias, relu / residual) ----------------
// BM=BN=128, BK=32, 256 threads (warps 4(M) x 2(N), warp tile 32x64), 4-stage cp.async.
// acc += Ahi*Bhi + Ahi*Blo + Alo*Bhi   (dropped lo*lo ~ 2^-18 relative)
template <bool RELU, bool RES, bool F32OUT>
__global__ void __launch_bounds__(256, 1)
gemm_kernel(const bf16* __restrict__ Ahi, const bf16* __restrict__ Alo,
            const bf16* __restrict__ Whi, const bf16* __restrict__ Wlo,
            const float* __restrict__ bias,
            const bf16* __restrict__ Rhi, const bf16* __restrict__ Rlo,
            bf16* __restrict__ Yhi, bf16* __restrict__ Ylo, float* __restrict__ Yf) {
    extern __shared__ char smem[];   // 4 stages x (A 16KB + B 16KB) = 128KB
    const int t = threadIdx.x;
    const int mBase = blockIdx.y * 128;
    const int nBase = blockIdx.x * 128;
    uint32_t smemBase = (uint32_t)__cvta_generic_to_shared(smem);

    // cp.async mapping: thread t -> row t>>1; even threads load the 64B hi segment
    // (chunks 0-3), odd threads the lo segment (chunks 4-7). Same for A and B.
    const int ldRow = t >> 1;
    const int half = t & 1;
    const bf16* aG = (half ? Alo : Ahi) + (size_t)(mBase + ldRow) * Dd;
    const bf16* bG = (half ? Wlo : Whi) + (size_t)(nBase + ldRow) * Dd;

    auto issue = [&](int kt, int stage) {
        uint32_t aB = smemBase + stage * 32768;
        uint32_t bB = aB + 16384;
        const bf16* ag = aG + (kt << 5);
        const bf16* bg = bG + (kt << 5);
#pragma unroll
        for (int i = 0; i < 4; i++) {
            asm volatile("cp.async.cg.shared.global [%0], [%1], 16;\n" ::
                         "r"(aB + swz(ldRow, half * 4 + i)), "l"(ag + i * 8));
            asm volatile("cp.async.cg.shared.global [%0], [%1], 16;\n" ::
                         "r"(bB + swz(ldRow, half * 4 + i)), "l"(bg + i * 8));
        }
    };

    const int lane = t & 31;
    const int warp = t >> 5;
    const int wm = warp & 3;
    const int wn = warp >> 2;

    float acc[2][8][4];
#pragma unroll
    for (int i = 0; i < 2; i++)
#pragma unroll
        for (int j = 0; j < 8; j++)
#pragma unroll
            for (int k = 0; k < 4; k++) acc[i][j][k] = 0.f;

    const int KT = Dd / 32;  // 32

#pragma unroll
    for (int s = 0; s < 3; s++) {
        issue(s, s);
        asm volatile("cp.async.commit_group;\n" ::: "memory");
    }

    // A frags: x4 -> [m0-7,klo][m8-15,klo][m0-7,khi][m8-15,khi]
    const int arowBase = wm * 32 + ((lane >> 3) & 1) * 8 + (lane & 7);
    const int achBase = lane >> 4;
    // B frags: x4 -> [n0-7,klo][n0-7,khi][n8-15,klo][n8-15,khi] per 16-row group
    const int brow = wn * 64 + (lane >> 4) * 8 + (lane & 7);
    const int bchBase = (lane >> 3) & 1;

    for (int kt = 0; kt < KT; kt++) {
        asm volatile("cp.async.wait_group 2;\n" ::: "memory");
        __syncthreads();
        if (kt + 3 < KT) issue(kt + 3, (kt + 3) & 3);
        asm volatile("cp.async.commit_group;\n" ::: "memory");

        uint32_t aS32 = smemBase + (kt & 3) * 32768;
        uint32_t bS32 = aS32 + 16384;
#pragma unroll
        for (int ks = 0; ks < 2; ks++) {
            uint32_t ah[2][4], al[2][4];
            int ach = (ks << 1) + achBase;
#pragma unroll
            for (int mt = 0; mt < 2; mt++) {
                ldsm4(ah[mt][0], ah[mt][1], ah[mt][2], ah[mt][3],
                      aS32 + swz(arowBase + mt * 16, ach));
                ldsm4(al[mt][0], al[mt][1], al[mt][2], al[mt][3],
                      aS32 + swz(arowBase + mt * 16, ach + 4));
            }
            uint32_t bh[8][2], bl[8][2];
            int bch = (ks << 1) + bchBase;
#pragma unroll
            for (int p = 0; p < 4; p++) {
                ldsm4(bh[2 * p][0], bh[2 * p][1], bh[2 * p + 1][0], bh[2 * p + 1][1],
                      bS32 + swz(brow + p * 16, bch));
                ldsm4(bl[2 * p][0], bl[2 * p][1], bl[2 * p + 1][0], bl[2 * p + 1][1],
                      bS32 + swz(brow + p * 16, bch + 4));
            }
#pragma unroll
            for (int mt = 0; mt < 2; mt++)
#pragma unroll
                for (int nt = 0; nt < 8; nt++) {
                    mma16816(acc[mt][nt], ah[mt], bh[nt]);
                    mma16816(acc[mt][nt], ah[mt], bl[nt]);
                    mma16816(acc[mt][nt], al[mt], bh[nt]);
                }
        }
    }

    // epilogue: lane -> (row lane>>2 [+8], cols 2(lane&3)+{0,1})
    int cr = mBase + wm * 32 + (lane >> 2);
    int cc = nBase + wn * 64 + ((lane & 3) << 1);
#pragma unroll
    for (int mt = 0; mt < 2; mt++) {
        int r0 = cr + mt * 16;
#pragma unroll
        for (int nt = 0; nt < 8; nt++) {
            int col = cc + nt * 8;
            float b0 = bias[col], b1 = bias[col + 1];
            float v0 = acc[mt][nt][0] + b0;
            float v1 = acc[mt][nt][1] + b1;
            float v2 = acc[mt][nt][2] + b0;
            float v3 = acc[mt][nt][3] + b1;
            if (RELU) {
                v0 = fmaxf(v0, 0.f); v1 = fmaxf(v1, 0.f);
                v2 = fmaxf(v2, 0.f); v3 = fmaxf(v3, 0.f);
            }
            size_t iA = (size_t)r0 * Dd + col;
            size_t iB = (size_t)(r0 + 8) * Dd + col;
            if (RES) {
                float2 rA = recon2(*reinterpret_cast<const uint32_t*>(Rhi + iA),
                                   *reinterpret_cast<const uint32_t*>(Rlo + iA));
                float2 rB = recon2(*reinterpret_cast<const uint32_t*>(Rhi + iB),
                                   *reinterpret_cast<const uint32_t*>(Rlo + iB));
                v0 += rA.x; v1 += rA.y; v2 += rB.x; v3 += rB.y;
            }
            if (F32OUT) {
                *reinterpret_cast<float2*>(Yf + iA) = make_float2(v0, v1);
                *reinterpret_cast<float2*>(Yf + iB) = make_float2(v2, v3);
            } else {
                uint32_t l01, l23;
                uint32_t h01 = pack_hi(v0, v1, l01);
                uint32_t h23 = pack_hi(v2, v3, l23);
                *reinterpret_cast<uint32_t*>(Yhi + iA) = h01;
                *reinterpret_cast<uint32_t*>(Ylo + iA) = l01;
                *reinterpret_cast<uint32_t*>(Yhi + iB) = h23;
                *reinterpret_cast<uint32_t*>(Ylo + iB) = l23;
            }
        }
    }
}

// ---------------- layernorm on hi/lo streams (in-place, one row per block) -----------
__global__ void ln_kernel(bf16* __restrict__ hh, bf16* __restrict__ hl,
                          const float* __restrict__ g, const float* __restrict__ b) {
    const int row = blockIdx.x;
    size_t base = (size_t)row * Dd + threadIdx.x * 4;
    uint2 ph = *reinterpret_cast<const uint2*>(hh + base);
    uint2 pl = *reinterpret_cast<const uint2*>(hl + base);
    float2 v01 = recon2(ph.x, pl.x);
    float2 v23 = recon2(ph.y, pl.y);
    float s = v01.x + v01.y + v23.x + v23.y;
    float q = v01.x * v01.x + v01.y * v01.y + v23.x * v23.x + v23.y * v23.y;
#pragma unroll
    for (int o = 16; o > 0; o >>= 1) {
        s += __shfl_xor_sync(0xffffffffu, s, o);
        q += __shfl_xor_sync(0xffffffffu, q, o);
    }
    __shared__ float ss[8], sq[8];
    int warp = threadIdx.x >> 5;
    if ((threadIdx.x & 31) == 0) { ss[warp] = s; sq[warp] = q; }
    __syncthreads();
    float ts = 0.f, tq = 0.f;
#pragma unroll
    for (int i = 0; i < 8; i++) { ts += ss[i]; tq += sq[i]; }
    float mean = ts * (1.0f / Dd);
    float var = tq * (1.0f / Dd) - mean * mean;   // population var (jnp.var)
    float rs = rsqrtf(var + 1e-5f);
    const float4 gg = *reinterpret_cast<const float4*>(g + threadIdx.x * 4);
    const float4 bb = *reinterpret_cast<const float4*>(b + threadIdx.x * 4);
    float o0 = (v01.x - mean) * rs * gg.x + bb.x;
    float o1 = (v01.y - mean) * rs * gg.y + bb.y;
    float o2 = (v23.x - mean) * rs * gg.z + bb.z;
    float o3 = (v23.y - mean) * rs * gg.w + bb.w;
    uint32_t l01, l23;
    uint32_t h01 = pack_hi(o0, o1, l01);
    uint32_t h23 = pack_hi(o2, o3, l23);
    *reinterpret_cast<uint2*>(hh + base) = make_uint2(h01, h23);
    *reinterpret_cast<uint2*>(hl + base) = make_uint2(l01, l23);
}

// ---------------- launcher ----------------
extern "C" void kernel_launch(void* const* d_in, const int* in_sizes, int n_in,
                              void* d_out, int out_size) {
    const float* x    = (const float*)d_in[0];
    const int*   qw   = (const int*)  d_in[1];
    const float* sc   = (const float*)d_in[2];
    const float* bias = (const float*)d_in[3];
    const float* la   = (const float*)d_in[4];
    const float* lb   = (const float*)d_in[5];
    const float* lng  = (const float*)d_in[6];
    const float* lnb  = (const float*)d_in[7];
    float* out = (float*)d_out;

    const int M = in_sizes[0] / Dd;  // 16384

    bf16 *Whi, *Wlo, *xh, *xl, *t1h, *t1l, *t2h, *t2l, *h0h, *h0l, *h1h, *h1l;
    cudaGetSymbolAddress((void**)&Whi, g_Whi);
    cudaGetSymbolAddress((void**)&Wlo, g_Wlo);
    cudaGetSymbolAddress((void**)&xh, g_xh);   cudaGetSymbolAddress((void**)&xl, g_xl);
    cudaGetSymbolAddress((void**)&t1h, g_t1h); cudaGetSymbolAddress((void**)&t1l, g_t1l);
    cudaGetSymbolAddress((void**)&t2h, g_t2h); cudaGetSymbolAddress((void**)&t2l, g_t2l);
    cudaGetSymbolAddress((void**)&h0h, g_h0h); cudaGetSymbolAddress((void**)&h0l, g_h0l);
    cudaGetSymbolAddress((void**)&h1h, g_h1h); cudaGetSymbolAddress((void**)&h1l, g_h1l);

    cudaFuncSetAttribute(gemm_kernel<true, false, false>,
                         cudaFuncAttributeMaxDynamicSharedMemorySize, 131072);
    cudaFuncSetAttribute(gemm_kernel<false, true, false>,
                         cudaFuncAttributeMaxDynamicSharedMemorySize, 131072);
    cudaFuncSetAttribute(gemm_kernel<false, true, true>,
                         cudaFuncAttributeMaxDynamicSharedMemorySize, 131072);

    prep_kernel<<<NLAYERS * 64, 256>>>(qw, sc, la, lb);
    split_kernel<<<((size_t)M * Dd / 4) / 256, 256>>>(x, xh, xl);

    dim3 grid(Dd / 128, M / 128);
    bf16* curH = xh; bf16* curL = xl;
    bf16* hpingH[2] = {h0h, h1h};
    bf16* hpingL[2] = {h0l, h1l};
    for (int blk = 0; blk < 6; blk++) {
        size_t w0 = (size_t)(blk * 3 + 0) * Dd * Dd;
        size_t w1 = (size_t)(blk * 3 + 1) * Dd * Dd;
        size_t w2 = (size_t)(blk * 3 + 2) * Dd * Dd;
        gemm_kernel<true, false, false><<<grid, 256, 131072>>>(
            curH, curL, Whi + w0, Wlo + w0, bias + (size_t)(blk * 3 + 0) * Dd,
            nullptr, nullptr, t1h, t1l, nullptr);
        gemm_kernel<true, false, false><<<grid, 256, 131072>>>(
            t1h, t1l, Whi + w1, Wlo + w1, bias + (size_t)(blk * 3 + 1) * Dd,
            nullptr, nullptr, t2h, t2l, nullptr);
        if (blk < 5) {
            bf16* hnH = hpingH[blk & 1];
            bf16* hnL = hpingL[blk & 1];
            gemm_kernel<false, true, false><<<grid, 256, 131072>>>(
                t2h, t2l, Whi + w2, Wlo + w2, bias + (size_t)(blk * 3 + 2) * Dd,
                curH, curL, hnH, hnL, nullptr);
            ln_kernel<<<M, 256>>>(hnH, hnL, lng + (size_t)blk * Dd, lnb + (size_t)blk * Dd);
            curH = hnH; curL = hnL;
        } else {
            gemm_kernel<false, true, true><<<grid, 256, 131072>>>(
                t2h, t2l, Whi + w2, Wlo + w2, bias + (size_t)(blk * 3 + 2) * Dd,
                curH, curL, nullptr, nullptr, out);
        }
    }
}

// round 16
// speedup vs baseline: 1.3520x; 1.3520x over previous
#include <cuda_runtime.h>
#include <cuda_bf16.h>
#include <stdint.h>

#define Dd      1024
#define NTOK    16384
#define NLAYERS 18
#define RLORA   32
#define QGROUP  16

typedef __nv_bfloat16 bf16;

// ---------------- scratch (__device__ globals; no allocation allowed) ----------------
__device__ bf16 g_Whi[(size_t)NLAYERS * Dd * Dd];
__device__ bf16 g_Wlo[(size_t)NLAYERS * Dd * Dd];
__device__ bf16 g_xh[(size_t)NTOK * Dd], g_xl[(size_t)NTOK * Dd];
__device__ bf16 g_t1h[(size_t)NTOK * Dd], g_t1l[(size_t)NTOK * Dd];
__device__ bf16 g_t2h[(size_t)NTOK * Dd], g_t2l[(size_t)NTOK * Dd];
__device__ bf16 g_h0h[(size_t)NTOK * Dd], g_h0l[(size_t)NTOK * Dd];
__device__ bf16 g_h1h[(size_t)NTOK * Dd], g_h1l[(size_t)NTOK * Dd];

// ---------------- helpers ----------------
__device__ __forceinline__ uint32_t pack_hi(float a, float b, uint32_t& lo) {
    bf16 ha = __float2bfloat16(a), hb = __float2bfloat16(b);
    __nv_bfloat162 L = __floats2bfloat162_rn(a - __bfloat162float(ha), b - __bfloat162float(hb));
    __nv_bfloat162 H = __halves2bfloat162(ha, hb);
    lo = *reinterpret_cast<uint32_t*>(&L);
    return *reinterpret_cast<uint32_t*>(&H);
}

__device__ __forceinline__ float2 recon2(uint32_t h, uint32_t l) {
    __nv_bfloat162 H = *reinterpret_cast<__nv_bfloat162*>(&h);
    __nv_bfloat162 L = *reinterpret_cast<__nv_bfloat162*>(&l);
    return make_float2(__bfloat162float(H.x) + __bfloat162float(L.x),
                       __bfloat162float(H.y) + __bfloat162float(L.y));
}

// ---------------- prep: smem-tiled dequant + LoRA fold + hi/lo split (unchanged) -----
__global__ void __launch_bounds__(256)
prep_kernel(const int* __restrict__ qw, const float* __restrict__ sc,
            const float* __restrict__ la, const float* __restrict__ lb) {
    __shared__ float la_s[8][1024];
    __shared__ float lb_s[16][32];
    const int l  = blockIdx.x >> 6;
    const int og = blockIdx.x & 63;
    const int t  = threadIdx.x;
    const int o_local = t >> 4;
    const int i0 = (t & 15) << 2;
    const int o  = og * 16 + o_local;

    if (t < 128) {
        int oo = t >> 3;
        int rr = (t & 7) << 2;
        *reinterpret_cast<float4*>(&lb_s[oo][rr]) =
            *reinterpret_cast<const float4*>(lb + ((size_t)l * Dd + og * 16 + oo) * RLORA + rr);
    }

    const size_t wrow = ((size_t)l * Dd + o) * Dd;
    const size_t srow = ((size_t)l * Dd + o) * (Dd / QGROUP);
    float4 acc[16];
#pragma unroll
    for (int j = 0; j < 16; j++) {
        int i = i0 + (j << 6);
        int4 q = *reinterpret_cast<const int4*>(qw + wrow + i);
        float s = sc[srow + (i >> 4)];
        acc[j] = make_float4(q.x * s, q.y * s, q.z * s, q.w * s);
    }

    for (int rc = 0; rc < 4; rc++) {
        __syncthreads();
#pragma unroll
        for (int v = 0; v < 8; v++) {
            int idx = v * 256 + t;
            int r = idx >> 8;
            int col = (idx & 255) << 2;
            *reinterpret_cast<float4*>(&la_s[r][col]) =
                *reinterpret_cast<const float4*>(la + ((size_t)l * RLORA + rc * 8 + r) * Dd + col);
        }
        __syncthreads();
#pragma unroll
        for (int r = 0; r < 8; r++) {
            float b = lb_s[o_local][rc * 8 + r];
#pragma unroll
            for (int j = 0; j < 16; j++) {
                const float4 v = *reinterpret_cast<const float4*>(&la_s[r][i0 + (j << 6)]);
                acc[j].x += b * v.x; acc[j].y += b * v.y;
                acc[j].z += b * v.z; acc[j].w += b * v.w;
            }
        }
    }

#pragma unroll
    for (int j = 0; j < 16; j++) {
        int i = i0 + (j << 6);
        uint32_t l01, l23;
        uint32_t h01 = pack_hi(acc[j].x, acc[j].y, l01);
        uint32_t h23 = pack_hi(acc[j].z, acc[j].w, l23);
        *reinterpret_cast<uint2*>(&g_Whi[wrow + i]) = make_uint2(h01, h23);
        *reinterpret_cast<uint2*>(&g_Wlo[wrow + i]) = make_uint2(l01, l23);
    }
}

// ---------------- split x (unchanged) ----------------
__global__ void split_kernel(const float* __restrict__ x, bf16* __restrict__ hi,
                             bf16* __restrict__ lo) {
    size_t i = ((size_t)blockIdx.x * blockDim.x + threadIdx.x) * 4;
    float4 v = *reinterpret_cast<const float4*>(x + i);
    uint32_t l01, l23;
    uint32_t h01 = pack_hi(v.x, v.y, l01);
    uint32_t h23 = pack_hi(v.z, v.w, l23);
    *reinterpret_cast<uint2*>(hi + i) = make_uint2(h01, h23);
    *reinterpret_cast<uint2*>(lo + i) = make_uint2(l01, l23);
}

// ---------------- GEMM helpers (unchanged) ----------------
// smem tile row = 128B: chunks 0-3 = hi (32 k-elems), 4-7 = lo. Swizzle: chunk ^= (row&7).
__device__ __forceinline__ uint32_t swz(int row, int chunk) {
    return (uint32_t)((row << 7) + ((chunk ^ (row & 7)) << 4));
}

__device__ __forceinline__ void ldsm4(uint32_t& r0, uint32_t& r1, uint32_t& r2, uint32_t& r3,
                                      uint32_t addr) {
    asm volatile("ldmatrix.sync.aligned.m8n8.x4.shared.b16 {%0,%1,%2,%3}, [%4];\n"
                 : "=r"(r0), "=r"(r1), "=r"(r2), "=r"(r3) : "r"(addr));
}

__device__ __forceinline__ void mma16816(float* c, const uint32_t* a, const uint32_t* b) {
    asm volatile("mma.sync.aligned.m16n8k16.row.col.f32.bf16.bf16.f32 "
                 "{%0,%1,%2,%3}, {%4,%5,%6,%7}, {%8,%9}, {%0,%1,%2,%3};\n"
                 : "+f"(c[0]), "+f"(c[1]), "+f"(c[2]), "+f"(c[3])
                 : "r"(a[0]), "r"(a[1]), "r"(a[2]), "r"(a[3]), "r"(b[0]), "r"(b[1]));
}

// ---------------- GEMM v2: 512 threads, warp grid 4(M) x 4(N), warp tile 32x32 -------
// BM=BN=128, BK=32, 4-stage cp.async (128KB smem). Same smem layout/swizzle as v1.
// acc += Ahi*Bhi + Ahi*Blo + Alo*Bhi   (lo*lo dropped, ~2^-18 relative)
template <bool RELU, bool RES, bool F32OUT>
__global__ void __launch_bounds__(512, 1)
gemm_kernel(const bf16* __restrict__ Ahi, const bf16* __restrict__ Alo,
            const bf16* __restrict__ Whi, const bf16* __restrict__ Wlo,
            const float* __restrict__ bias,
            const bf16* __restrict__ Rhi, const bf16* __restrict__ Rlo,
            bf16* __restrict__ Yhi, bf16* __restrict__ Ylo, float* __restrict__ Yf) {
    extern __shared__ char smem[];   // 4 stages x (A 16KB + B 16KB) = 128KB
    const int t = threadIdx.x;
    const int mBase = blockIdx.y * 128;
    const int nBase = blockIdx.x * 128;
    uint32_t smemBase = (uint32_t)__cvta_generic_to_shared(smem);

    // loader: 512 threads. t -> row = t>>2 (0..127); sub = t&3 selects
    // (half = sub>>1: hi/lo stream) and (chunk pair i0 = (sub&1)*2 within that half).
    // 2 cp.async for A + 2 for B per thread = 32KB/stage total.
    const int ldRow = t >> 2;
    const int sub = t & 3;
    const int half = sub >> 1;
    const int i0ld = (sub & 1) << 1;     // 0 or 2 (chunk index within the 4-chunk half)
    const bf16* aG = (half ? Alo : Ahi) + (size_t)(mBase + ldRow) * Dd + i0ld * 8;
    const bf16* bG = (half ? Wlo : Whi) + (size_t)(nBase + ldRow) * Dd + i0ld * 8;

    auto issue = [&](int kt, int stage) {
        uint32_t aB = smemBase + stage * 32768;
        uint32_t bB = aB + 16384;
        const bf16* ag = aG + (kt << 5);
        const bf16* bg = bG + (kt << 5);
#pragma unroll
        for (int i = 0; i < 2; i++) {
            int ch = half * 4 + i0ld + i;
            asm volatile("cp.async.cg.shared.global [%0], [%1], 16;\n" ::
                         "r"(aB + swz(ldRow, ch)), "l"(ag + i * 8));
            asm volatile("cp.async.cg.shared.global [%0], [%1], 16;\n" ::
                         "r"(bB + swz(ldRow, ch)), "l"(bg + i * 8));
        }
    };

    const int lane = t & 31;
    const int warp = t >> 5;      // 0..15
    const int wm = warp & 3;      // M tile: wm*32
    const int wn = warp >> 2;     // N tile: wn*32 (0..3)

    float acc[2][4][4];
#pragma unroll
    for (int i = 0; i < 2; i++)
#pragma unroll
        for (int j = 0; j < 4; j++)
#pragma unroll
            for (int k = 0; k < 4; k++) acc[i][j][k] = 0.f;

    const int KT = Dd / 32;  // 32

#pragma unroll
    for (int s = 0; s < 3; s++) {
        issue(s, s);
        asm volatile("cp.async.commit_group;\n" ::: "memory");
    }

    // A frags (identical mapping to v1): x4 -> two m8 groups x two k8 chunks
    const int arowBase = wm * 32 + ((lane >> 3) & 1) * 8 + (lane & 7);
    const int achBase = lane >> 4;
    // B frags: warp covers 32 N-rows; x4 at 16-row group p covers two n8 tiles
    const int brow = wn * 32 + (lane >> 4) * 8 + (lane & 7);
    const int bchBase = (lane >> 3) & 1;

    for (int kt = 0; kt < KT; kt++) {
        asm volatile("cp.async.wait_group 2;\n" ::: "memory");
        __syncthreads();
        if (kt + 3 < KT) issue(kt + 3, (kt + 3) & 3);
        asm volatile("cp.async.commit_group;\n" ::: "memory");

        uint32_t aS32 = smemBase + (kt & 3) * 32768;
        uint32_t bS32 = aS32 + 16384;
#pragma unroll
        for (int ks = 0; ks < 2; ks++) {
            uint32_t ah[2][4], al[2][4];
            int ach = (ks << 1) + achBase;
#pragma unroll
            for (int mt = 0; mt < 2; mt++) {
                ldsm4(ah[mt][0], ah[mt][1], ah[mt][2], ah[mt][3],
                      aS32 + swz(arowBase + mt * 16, ach));
                ldsm4(al[mt][0], al[mt][1], al[mt][2], al[mt][3],
                      aS32 + swz(arowBase + mt * 16, ach + 4));
            }
            uint32_t bh[4][2], bl[4][2];
            int bch = (ks << 1) + bchBase;
#pragma unroll
            for (int p = 0; p < 2; p++) {
                ldsm4(bh[2 * p][0], bh[2 * p][1], bh[2 * p + 1][0], bh[2 * p + 1][1],
                      bS32 + swz(brow + p * 16, bch));
                ldsm4(bl[2 * p][0], bl[2 * p][1], bl[2 * p + 1][0], bl[2 * p + 1][1],
                      bS32 + swz(brow + p * 16, bch + 4));
            }
#pragma unroll
            for (int mt = 0; mt < 2; mt++)
#pragma unroll
                for (int nt = 0; nt < 4; nt++) {
                    mma16816(acc[mt][nt], ah[mt], bh[nt]);
                    mma16816(acc[mt][nt], ah[mt], bl[nt]);
                    mma16816(acc[mt][nt], al[mt], bh[nt]);
                }
        }
    }

    // epilogue: lane -> (row lane>>2 [+8], cols 2(lane&3)+{0,1}); warp cols wn*32
    int cr = mBase + wm * 32 + (lane >> 2);
    int cc = nBase + wn * 32 + ((lane & 3) << 1);
#pragma unroll
    for (int mt = 0; mt < 2; mt++) {
        int r0 = cr + mt * 16;
#pragma unroll
        for (int nt = 0; nt < 4; nt++) {
            int col = cc + nt * 8;
            float b0 = bias[col], b1 = bias[col + 1];
            float v0 = acc[mt][nt][0] + b0;
            float v1 = acc[mt][nt][1] + b1;
            float v2 = acc[mt][nt][2] + b0;
            float v3 = acc[mt][nt][3] + b1;
            if (RELU) {
                v0 = fmaxf(v0, 0.f); v1 = fmaxf(v1, 0.f);
                v2 = fmaxf(v2, 0.f); v3 = fmaxf(v3, 0.f);
            }
            size_t iA = (size_t)r0 * Dd + col;
            size_t iB = (size_t)(r0 + 8) * Dd + col;
            if (RES) {
                float2 rA = recon2(*reinterpret_cast<const uint32_t*>(Rhi + iA),
                                   *reinterpret_cast<const uint32_t*>(Rlo + iA));
                float2 rB = recon2(*reinterpret_cast<const uint32_t*>(Rhi + iB),
                                   *reinterpret_cast<const uint32_t*>(Rlo + iB));
                v0 += rA.x; v1 += rA.y; v2 += rB.x; v3 += rB.y;
            }
            if (F32OUT) {
                *reinterpret_cast<float2*>(Yf + iA) = make_float2(v0, v1);
                *reinterpret_cast<float2*>(Yf + iB) = make_float2(v2, v3);
            } else {
                uint32_t l01, l23;
                uint32_t h01 = pack_hi(v0, v1, l01);
                uint32_t h23 = pack_hi(v2, v3, l23);
                *reinterpret_cast<uint32_t*>(Yhi + iA) = h01;
                *reinterpret_cast<uint32_t*>(Ylo + iA) = l01;
                *reinterpret_cast<uint32_t*>(Yhi + iB) = h23;
                *reinterpret_cast<uint32_t*>(Ylo + iB) = l23;
            }
        }
    }
}

// ---------------- layernorm on hi/lo streams (unchanged) ----------------
__global__ void ln_kernel(bf16* __restrict__ hh, bf16* __restrict__ hl,
                          const float* __restrict__ g, const float* __restrict__ b) {
    const int row = blockIdx.x;
    size_t base = (size_t)row * Dd + threadIdx.x * 4;
    uint2 ph = *reinterpret_cast<const uint2*>(hh + base);
    uint2 pl = *reinterpret_cast<const uint2*>(hl + base);
    float2 v01 = recon2(ph.x, pl.x);
    float2 v23 = recon2(ph.y, pl.y);
    float s = v01.x + v01.y + v23.x + v23.y;
    float q = v01.x * v01.x + v01.y * v01.y + v23.x * v23.x + v23.y * v23.y;
#pragma unroll
    for (int o = 16; o > 0; o >>= 1) {
        s += __shfl_xor_sync(0xffffffffu, s, o);
        q += __shfl_xor_sync(0xffffffffu, q, o);
    }
    __shared__ float ss[8], sq[8];
    int warp = threadIdx.x >> 5;
    if ((threadIdx.x & 31) == 0) { ss[warp] = s; sq[warp] = q; }
    __syncthreads();
    float ts = 0.f, tq = 0.f;
#pragma unroll
    for (int i = 0; i < 8; i++) { ts += ss[i]; tq += sq[i]; }
    float mean = ts * (1.0f / Dd);
    float var = tq * (1.0f / Dd) - mean * mean;   // population var (jnp.var)
    float rs = rsqrtf(var + 1e-5f);
    const float4 gg = *reinterpret_cast<const float4*>(g + threadIdx.x * 4);
    const float4 bb = *reinterpret_cast<const float4*>(b + threadIdx.x * 4);
    float o0 = (v01.x - mean) * rs * gg.x + bb.x;
    float o1 = (v01.y - mean) * rs * gg.y + bb.y;
    float o2 = (v23.x - mean) * rs * gg.z + bb.z;
    float o3 = (v23.y - mean) * rs * gg.w + bb.w;
    uint32_t l01, l23;
    uint32_t h01 = pack_hi(o0, o1, l01);
    uint32_t h23 = pack_hi(o2, o3, l23);
    *reinterpret_cast<uint2*>(hh + base) = make_uint2(h01, h23);
    *reinterpret_cast<uint2*>(hl + base) = make_uint2(l01, l23);
}

// ---------------- launcher ----------------
extern "C" void kernel_launch(void* const* d_in, const int* in_sizes, int n_in,
                              void* d_out, int out_size) {
    const float* x    = (const float*)d_in[0];
    const int*   qw   = (const int*)  d_in[1];
    const float* sc   = (const float*)d_in[2];
    const float* bias = (const float*)d_in[3];
    const float* la   = (const float*)d_in[4];
    const float* lb   = (const float*)d_in[5];
    const float* lng  = (const float*)d_in[6];
    const float* lnb  = (const float*)d_in[7];
    float* out = (float*)d_out;

    const int M = in_sizes[0] / Dd;  // 16384

    bf16 *Whi, *Wlo, *xh, *xl, *t1h, *t1l, *t2h, *t2l, *h0h, *h0l, *h1h, *h1l;
    cudaGetSymbolAddress((void**)&Whi, g_Whi);
    cudaGetSymbolAddress((void**)&Wlo, g_Wlo);
    cudaGetSymbolAddress((void**)&xh, g_xh);   cudaGetSymbolAddress((void**)&xl, g_xl);
    cudaGetSymbolAddress((void**)&t1h, g_t1h); cudaGetSymbolAddress((void**)&t1l, g_t1l);
    cudaGetSymbolAddress((void**)&t2h, g_t2h); cudaGetSymbolAddress((void**)&t2l, g_t2l);
    cudaGetSymbolAddress((void**)&h0h, g_h0h); cudaGetSymbolAddress((void**)&h0l, g_h0l);
    cudaGetSymbolAddress((void**)&h1h, g_h1h); cudaGetSymbolAddress((void**)&h1l, g_h1l);

    cudaFuncSetAttribute(gemm_kernel<true, false, false>,
                         cudaFuncAttributeMaxDynamicSharedMemorySize, 131072);
    cudaFuncSetAttribute(gemm_kernel<false, true, false>,
                         cudaFuncAttributeMaxDynamicSharedMemorySize, 131072);
    cudaFuncSetAttribute(gemm_kernel<false, true, true>,
                         cudaFuncAttributeMaxDynamicSharedMemorySize, 131072);

    prep_kernel<<<NLAYERS * 64, 256>>>(qw, sc, la, lb);
    split_kernel<<<((size_t)M * Dd / 4) / 256, 256>>>(x, xh, xl);

    dim3 grid(Dd / 128, M / 128);
    bf16* curH = xh; bf16* curL = xl;
    bf16* hpingH[2] = {h0h, h1h};
    bf16* hpingL[2] = {h0l, h1l};
    for (int blk = 0; blk < 6; blk++) {
        size_t w0 = (size_t)(blk * 3 + 0) * Dd * Dd;
        size_t w1 = (size_t)(blk * 3 + 1) * Dd * Dd;
        size_t w2 = (size_t)(blk * 3 + 2) * Dd * Dd;
        gemm_kernel<true, false, false><<<grid, 512, 131072>>>(
            curH, curL, Whi + w0, Wlo + w0, bias + (size_t)(blk * 3 + 0) * Dd,
            nullptr, nullptr, t1h, t1l, nullptr);
        gemm_kernel<true, false, false><<<grid, 512, 131072>>>(
            t1h, t1l, Whi + w1, Wlo + w1, bias + (size_t)(blk * 3 + 1) * Dd,
            nullptr, nullptr, t2h, t2l, nullptr);
        if (blk < 5) {
            bf16* hnH = hpingH[blk & 1];
            bf16* hnL = hpingL[blk & 1];
            gemm_kernel<false, true, false><<<grid, 512, 131072>>>(
                t2h, t2l, Whi + w2, Wlo + w2, bias + (size_t)(blk * 3 + 2) * Dd,
                curH, curL, hnH, hnL, nullptr);
            ln_kernel<<<M, 256>>>(hnH, hnL, lng + (size_t)blk * Dd, lnb + (size_t)blk * Dd);
            curH = hnH; curL = hnL;
        } else {
            gemm_kernel<false, true, true><<<grid, 512, 131072>>>(
                t2h, t2l, Whi + w2, Wlo + w2, bias + (size_t)(blk * 3 + 2) * Dd,
                curH, curL, nullptr, nullptr, out);
        }
    }
}